// round 5
// baseline (speedup 1.0000x reference)
#include <cuda_runtime.h>
#include <cstdint>

// OptimizedUniformSampler: KGE negative sampling + sorted-hash filter.
// Inputs identified by size (order-independent). Input width detected on
// device (int32 vs int64). OUTPUT IS FLOAT32: neg [T*3] then keep [T].
// Search replicates bisect_left exactly (table may be unsorted after int32
// truncation); first 12 levels served from a precomputed smem bisect tree.

#define TREE_LVLS 12
#define TREE_SLOTS 4096   // 2^TREE_LVLS
#define EPT 16
#define THREADS 256

__device__ int g_width;

__global__ void detect_kernel(const unsigned int* __restrict__ pw, int n_words) {
    if (threadIdx.x == 0) {
        int w = 8;
        int lim = n_words < 64 ? n_words : 64;
        for (int k = 1; k < lim; k += 2)
            if (pw[k] != 0u) { w = 4; break; }
        g_width = w;
    }
}

__global__ __launch_bounds__(THREADS)
void sampler_kernel(const void* __restrict__ posv,
                    const void* __restrict__ randv,
                    const void* __restrict__ hashv,
                    float* __restrict__ out,       // [>= 3T (+T)] float32
                    int total, int negs, int L,
                    int write_neg, long long keep_budget)
{
    __shared__ long long tree[TREE_SLOTS];   // implicit bisect tree, levels 0..11
    const int W = g_width;
    const long long T = total;
    const int split = (total + 1) >> 1;
    const int base = blockIdx.x * (THREADS * EPT);

    // ---- build smem bisect tree (node t: path bits below MSB pick branches) ----
    for (int t = 1 + threadIdx.x; t < TREE_SLOTS; t += THREADS) {
        // depth = position of MSB
        int msb = 31 - __clz(t);
        int lo = 0, hi = L;
        for (int b = msb - 1; b >= 0; b--) {
            if (lo >= hi) break;
            int mid = (lo + hi) >> 1;
            if ((t >> b) & 1) lo = mid + 1; else hi = mid;
        }
        long long v = 0x7fffffffffffffffLL;  // sentinel (unreached paths)
        if (lo < hi) {
            int mid = (lo + hi) >> 1;
            v = (W == 8) ? __ldg(&((const long long*)hashv)[mid])
                         : (long long)__ldg(&((const int*)hashv)[mid]);
        }
        tree[t] = v;
    }
    __syncthreads();

    #pragma unroll 4
    for (int j = 0; j < EPT; j++) {
        int i = base + j * THREADS + threadIdx.x;
        if (i >= total) break;
        int b = i / negs;

        long long e0, r1, e2, rv;
        if (W == 8) {
            const long long* pos = (const long long*)posv;
            e0 = __ldg(&pos[(long long)b * 3 + 0]);
            r1 = __ldg(&pos[(long long)b * 3 + 1]);
            e2 = __ldg(&pos[(long long)b * 3 + 2]);
            rv = __ldg(&((const long long*)randv)[i]);
        } else {
            const int* pos = (const int*)posv;
            e0 = __ldg(&pos[b * 3 + 0]);
            r1 = __ldg(&pos[b * 3 + 1]);
            e2 = __ldg(&pos[b * 3 + 2]);
            rv = __ldg(&((const int*)randv)[i]);
        }

        bool chd = (i < split);
        long long orig = chd ? e0 : e2;
        long long repl = rv + (((rv >= orig) && (orig > 0)) ? 1LL : 0LL);
        if (chd) e0 = repl; else e2 = repl;

        // hash: int64 path = full hash; int32 path = x64-off semantics
        // (e0<<42 on int32 -> 0), table truncated the same way.
        long long h;
        if (W == 8) h = (e0 << 42) | (r1 << 21) | e2;
        else        h = (long long)(int)(((int)r1 << 21) | (int)e2);

        // ---- bisect_left, levels 0..11 from smem tree ----
        int lo = 0, hi = L, node = 1;
        #pragma unroll
        for (int lvl = 0; lvl < TREE_LVLS; lvl++) {
            if (lo >= hi) break;
            int mid = (lo + hi) >> 1;
            if (tree[node] < h) { lo = mid + 1; node = 2 * node + 1; }
            else                { hi = mid;     node = 2 * node;     }
        }
        // ---- tail in global ----
        if (W == 8) {
            const long long* hs = (const long long*)hashv;
            while (lo < hi) { int m = (lo + hi) >> 1;
                              if (__ldg(&hs[m]) < h) lo = m + 1; else hi = m; }
        } else {
            const int* hs = (const int*)hashv;
            int h32 = (int)h;
            while (lo < hi) { int m = (lo + hi) >> 1;
                              if (__ldg(&hs[m]) < h32) lo = m + 1; else hi = m; }
        }
        bool in_set;
        if (W == 8) in_set = (lo < L) && (__ldg(&((const long long*)hashv)[lo]) == h);
        else        in_set = (lo < L) && (__ldg(&((const int*)hashv)[lo]) == (int)h);

        // ---- float32 stores: neg [0,3T), keep [3T,4T) ----
        if (write_neg) {
            long long o = (long long)i * 3;
            out[o + 0] = (float)e0;
            out[o + 1] = (float)r1;
            out[o + 2] = (float)e2;
        }
        if ((long long)i < keep_budget)
            out[3 * T + i] = in_set ? 0.0f : 1.0f;
    }
}

extern "C" void kernel_launch(void* const* d_in, const int* in_sizes, int n_in,
                              void* d_out, int out_size) {
    // order-independent identification by size: pos < hashes < rand
    int idx[3]; int cnt = 0;
    for (int k = 0; k < n_in && cnt < 3; k++)
        if (in_sizes[k] > 1) idx[cnt++] = k;
    for (int a = 0; a < cnt; a++)
        for (int c = a + 1; c < cnt; c++)
            if (in_sizes[idx[c]] < in_sizes[idx[a]]) { int t = idx[a]; idx[a] = idx[c]; idx[c] = t; }

    int i_pos = idx[0], i_hash = idx[1], i_rand = idx[2];
    const void* pos    = d_in[i_pos];
    const void* hashes = d_in[i_hash];
    const void* rv     = d_in[i_rand];

    int total = in_sizes[i_rand];
    int B     = in_sizes[i_pos] / 3;
    int L     = in_sizes[i_hash];
    int negs  = (B > 0) ? total / B : 1;
    if (negs < 1) negs = 1;

    long long T = total;
    long long oe = out_size;
    int write_neg = (oe >= 3 * T) ? 1 : 0;
    long long keep_budget = write_neg ? (oe - 3 * T) : 0;  // elements available after neg
    if (keep_budget > T) keep_budget = T;
    if (!write_neg) keep_budget = 0;                       // (unknown tiny layout: write nothing risky)

    detect_kernel<<<1, 32>>>((const unsigned int*)pos, in_sizes[i_pos]);

    int per_block = THREADS * EPT;
    int grid = (total + per_block - 1) / per_block;
    sampler_kernel<<<grid, THREADS>>>(pos, rv, hashes, (float*)d_out,
                                      total, negs, L, write_neg, keep_budget);
}